// round 8
// baseline (speedup 1.0000x reference)
#include <cuda_runtime.h>
#include <cuda_bf16.h>
#include <cstdint>

#define N_TOK 16384
#define HID   768
#define INTER 3072
#define NH    12
#define DH    64
#define MIDW  5376   // 3*HID + INTER
#define COMBW 3840   // HID + INTER
#define QKVW  2304   // 3*HID

typedef unsigned long long ull;

// ================= scratch (device globals) =================
__device__ float         g_xn   [N_TOK * HID];
__device__ __nv_bfloat16 g_xn_h [N_TOK * HID];
__device__ __nv_bfloat16 g_xn_l [N_TOK * HID];
__device__ __nv_bfloat16 g_qkv_h[(size_t)N_TOK * QKVW];
__device__ __nv_bfloat16 g_qkv_l[(size_t)N_TOK * QKVW];
__device__ __nv_bfloat16 g_cmb_h[(size_t)N_TOK * COMBW];
__device__ __nv_bfloat16 g_cmb_l[(size_t)N_TOK * COMBW];
__device__ __nv_bfloat16 g_winT_h[(size_t)MIDW * HID];
__device__ __nv_bfloat16 g_winT_l[(size_t)MIDW * HID];
__device__ __nv_bfloat16 g_woutT_h[(size_t)HID * COMBW];
__device__ __nv_bfloat16 g_woutT_l[(size_t)HID * COMBW];

// ================= helpers =================
__device__ __forceinline__ uint32_t smem_to_u32(const void* p) {
    uint32_t a;
    asm("{ .reg .u64 t; cvta.to.shared.u64 t, %1; cvt.u32.u64 %0, t; }" : "=r"(a) : "l"(p));
    return a;
}
#define SMEM_SWIZZLE_128B(bo) ((bo) ^ (((bo) >> 3) & 0x70))

__device__ __forceinline__ void cp_async16(uint32_t saddr, const void* gaddr) {
    asm volatile("cp.async.cg.shared.global [%0], [%1], 16;" :: "r"(saddr), "l"(gaddr));
}
__device__ __forceinline__ void cp_async16z(uint32_t saddr, const void* gaddr, int srcsz) {
    asm volatile("cp.async.cg.shared.global [%0], [%1], 16, %2;"
                 :: "r"(saddr), "l"(gaddr), "r"(srcsz));
}
#define CP_COMMIT() asm volatile("cp.async.commit_group;" ::: "memory")

__device__ __forceinline__ void ldsm4(uint32_t r[4], uint32_t addr) {
    asm volatile("ldmatrix.sync.aligned.m8n8.x4.shared.b16 {%0,%1,%2,%3}, [%4];"
        : "=r"(r[0]), "=r"(r[1]), "=r"(r[2]), "=r"(r[3]) : "r"(addr));
}
__device__ __forceinline__ void ldsm4t(uint32_t r[4], uint32_t addr) {
    asm volatile("ldmatrix.sync.aligned.m8n8.x4.trans.shared.b16 {%0,%1,%2,%3}, [%4];"
        : "=r"(r[0]), "=r"(r[1]), "=r"(r[2]), "=r"(r[3]) : "r"(addr));
}
__device__ __forceinline__ void mma16816(float c[4], const uint32_t a[4], const uint32_t b[2]) {
    asm volatile(
        "mma.sync.aligned.m16n8k16.row.col.f32.bf16.bf16.f32 "
        "{%0,%1,%2,%3}, {%4,%5,%6,%7}, {%8,%9}, {%0,%1,%2,%3};"
        : "+f"(c[0]), "+f"(c[1]), "+f"(c[2]), "+f"(c[3])
        : "r"(a[0]), "r"(a[1]), "r"(a[2]), "r"(a[3]), "r"(b[0]), "r"(b[1]));
}

__device__ __forceinline__ void split_bf16(float x, __nv_bfloat16& h, __nv_bfloat16& l) {
    h = __float2bfloat16(x);
    l = __float2bfloat16(x - __bfloat162float(h));
}
__device__ __forceinline__ uint32_t pack_b(__nv_bfloat16 a, __nv_bfloat16 b) {
    __nv_bfloat162 t; t.x = a; t.y = b;
    return *(uint32_t*)&t;
}

__device__ __forceinline__ float gelu_tanh(float x) {
    float x3 = x * x * x;
    float u = 0.7978845608028654f * fmaf(0.044715f, x3, x);
    return 0.5f * x * (1.f + tanhf(u));
}

// ============================================================
// LayerNorm: one block per row; writes fp32 xn + bf16 hi/lo
// ============================================================
__global__ __launch_bounds__(256) void ln_kernel(
    const float* __restrict__ x, const float* __restrict__ gamma,
    const float* __restrict__ beta, float* __restrict__ xn,
    __nv_bfloat16* __restrict__ xh, __nv_bfloat16* __restrict__ xl)
{
    const int row = blockIdx.x;
    const int tid = threadIdx.x;
    const float* xr = x + (size_t)row * HID;
    float v0 = xr[tid], v1 = xr[tid + 256], v2 = xr[tid + 512];
    float s  = v0 + v1 + v2;
    float sq = v0 * v0 + v1 * v1 + v2 * v2;
    #pragma unroll
    for (int o = 16; o > 0; o >>= 1) {
        s  += __shfl_xor_sync(0xffffffffu, s,  o);
        sq += __shfl_xor_sync(0xffffffffu, sq, o);
    }
    __shared__ float ss[8], sqs[8];
    __shared__ float mu_s, rstd_s;
    if ((tid & 31) == 0) { ss[tid >> 5] = s; sqs[tid >> 5] = sq; }
    __syncthreads();
    if (tid == 0) {
        float S = 0.f, SQ = 0.f;
        #pragma unroll
        for (int i = 0; i < 8; i++) { S += ss[i]; SQ += sqs[i]; }
        float mu  = S * (1.0f / HID);
        float var = SQ * (1.0f / HID) - mu * mu;
        mu_s = mu;
        rstd_s = rsqrtf(var + 1e-5f);
    }
    __syncthreads();
    float mu = mu_s, r = rstd_s;
    size_t base = (size_t)row * HID;
    #pragma unroll
    for (int it = 0; it < 3; it++) {
        int c = tid + it * 256;
        float v = (it == 0) ? v0 : (it == 1) ? v1 : v2;
        float y = (v - mu) * r * gamma[c] + beta[c];
        xn[base + c] = y;
        __nv_bfloat16 h, l;
        split_bf16(y, h, l);
        xh[base + c] = h;
        xl[base + c] = l;
    }
}

// ============================================================
// Weight transpose + bf16 hi/lo split: W[K,N] -> T[N,K]
// ============================================================
__global__ __launch_bounds__(256) void wtr_kernel(
    const float* __restrict__ W, __nv_bfloat16* __restrict__ Th,
    __nv_bfloat16* __restrict__ Tl, int K, int N)
{
    __shared__ float t[32][33];
    const int nb = blockIdx.x * 32, kb = blockIdx.y * 32;
    const int x = threadIdx.x & 31, y = threadIdx.x >> 5;
    #pragma unroll
    for (int j = 0; j < 32; j += 8)
        t[y + j][x] = W[(size_t)(kb + y + j) * N + nb + x];
    __syncthreads();
    #pragma unroll
    for (int j = 0; j < 32; j += 8) {
        float v = t[x][y + j];
        __nv_bfloat16 h, l;
        split_bf16(v, h, l);
        size_t o = (size_t)(nb + y + j) * K + kb + x;
        Th[o] = h;
        Tl[o] = l;
    }
}

// ============================================================
// HMMA GEMM with register-level fragment double-buffering.
// 128x128 CTA tile, K-chunk 64, cp.async 2-stage, 8 warps (2x4),
// warp tile 64x32, mma.sync m16n8k16 bf16, fp32 accum, 3-term split.
// EPI=1: bias + rope(q,k) + 0.125 fold (q) -> qkv bf16 h/l; gelu -> comb h/l
// EPI=0: bias + residual -> out
// ============================================================
#define GEMM_SMEM (2 * 65536)

template<int EPI>
__global__ __launch_bounds__(256, 1) void gemm_kernel(
    const __nv_bfloat16* __restrict__ Ah, const __nv_bfloat16* __restrict__ Al,
    const __nv_bfloat16* __restrict__ Bh, const __nv_bfloat16* __restrict__ Bl,
    int K, const float* __restrict__ bias,
    const float* __restrict__ psin, const float* __restrict__ pcos,
    __nv_bfloat16* __restrict__ qkvh, __nv_bfloat16* __restrict__ qkvl,
    __nv_bfloat16* __restrict__ Ch, __nv_bfloat16* __restrict__ Cl,
    const float* __restrict__ resid, float* __restrict__ outp)
{
    extern __shared__ char smem[];
    const uint32_t sb = smem_to_u32(smem);
    const int tid = threadIdx.x;
    const int wid = tid >> 5, lane = tid & 31;
    const int bn = blockIdx.x, bm = blockIdx.y;
    const int wm = wid >> 2, wn = wid & 3;     // 2 x 4 warp grid
    const int NC = K >> 6;

    float acc[4][4][4];
    #pragma unroll
    for (int i = 0; i < 4; i++)
        #pragma unroll
        for (int j = 0; j < 4; j++)
            #pragma unroll
            for (int e = 0; e < 4; e++) acc[i][j][e] = 0.f;

    const int lm_mat = lane >> 3, lm_r = lane & 7;
    const int ld_r = tid >> 3, ld_c = tid & 7;

    #define LOAD_CHUNK(ck) do {                                                   \
        const uint32_t stg = sb + ((ck) & 1) * 65536;                             \
        const int kc = (ck) << 6;                                                 \
        _Pragma("unroll")                                                         \
        for (int it = 0; it < 4; it++) {                                          \
            int r = ld_r + it * 32;                                               \
            uint32_t so = SMEM_SWIZZLE_128B((uint32_t)(r * 128 + ld_c * 16));     \
            size_t rowA = (size_t)(bm * 128 + r) * K + kc + ld_c * 8;             \
            size_t rowB = (size_t)(bn * 128 + r) * K + kc + ld_c * 8;             \
            cp_async16(stg + so,         Ah + rowA);                              \
            cp_async16(stg + 16384 + so, Al + rowA);                              \
            cp_async16(stg + 32768 + so, Bh + rowB);                              \
            cp_async16(stg + 49152 + so, Bl + rowB);                              \
        }                                                                         \
        CP_COMMIT();                                                              \
    } while (0)

    // ldsm fragments for one k-step into buffer b (12 x ldsm4)
    #define LOAD_FRAGS(ks, b) do {                                                \
        _Pragma("unroll")                                                         \
        for (int mi = 0; mi < 4; mi++) {                                          \
            int row  = wm * 64 + mi * 16 + lm_r + (lm_mat & 1) * 8;               \
            int kcol = (ks) * 16 + (lm_mat >> 1) * 8;                             \
            uint32_t so = SMEM_SWIZZLE_128B((uint32_t)(row * 128 + kcol * 2));    \
            ldsm4(fah[b][mi], sA + so);                                           \
            ldsm4(fal[b][mi], sA + 16384 + so);                                   \
        }                                                                         \
        _Pragma("unroll")                                                         \
        for (int jp = 0; jp < 2; jp++) {                                          \
            int row  = wn * 32 + (jp * 2 + (lm_mat >> 1)) * 8 + lm_r;             \
            int kcol = (ks) * 16 + (lm_mat & 1) * 8;                              \
            uint32_t so = SMEM_SWIZZLE_128B((uint32_t)(row * 128 + kcol * 2));    \
            uint32_t t[4];                                                        \
            ldsm4(t, sB + so);                                                    \
            fbh[b][jp * 2][0] = t[0]; fbh[b][jp * 2][1] = t[1];                   \
            fbh[b][jp * 2 + 1][0] = t[2]; fbh[b][jp * 2 + 1][1] = t[3];           \
            ldsm4(t, sB + 16384 + so);                                            \
            fbl[b][jp * 2][0] = t[0]; fbl[b][jp * 2][1] = t[1];                   \
            fbl[b][jp * 2 + 1][0] = t[2]; fbl[b][jp * 2 + 1][1] = t[3];           \
        }                                                                         \
    } while (0)

    uint32_t fah[2][4][4], fal[2][4][4], fbh[2][4][2], fbl[2][4][2];

    LOAD_CHUNK(0);

    for (int ck = 0; ck < NC; ck++) {
        if (ck + 1 < NC) {
            LOAD_CHUNK(ck + 1);
            asm volatile("cp.async.wait_group 1;" ::: "memory");
        } else {
            asm volatile("cp.async.wait_group 0;" ::: "memory");
        }
        __syncthreads();

        const uint32_t sA = sb + (ck & 1) * 65536;
        const uint32_t sB = sA + 32768;

        LOAD_FRAGS(0, 0);   // prologue: k-step 0 into buffer 0
        #pragma unroll
        for (int ks = 0; ks < 4; ks++) {
            const int cur = ks & 1;
            if (ks < 3) LOAD_FRAGS(ks + 1, cur ^ 1);   // overlap next ldsm with MMAs
            #pragma unroll
            for (int mi = 0; mi < 4; mi++)
                #pragma unroll
                for (int nj = 0; nj < 4; nj++) {
                    mma16816(acc[mi][nj], fah[cur][mi], fbh[cur][nj]);
                    mma16816(acc[mi][nj], fah[cur][mi], fbl[cur][nj]);
                    mma16816(acc[mi][nj], fal[cur][mi], fbh[cur][nj]);
                }
        }
        __syncthreads();
    }
    #undef LOAD_CHUNK
    #undef LOAD_FRAGS

    // ---------------- epilogue ----------------
    const int r0 = bm * 128 + wm * 64 + (lane >> 2);
    const int c0 = bn * 128 + wn * 32 + (lane & 3) * 2;

    #pragma unroll
    for (int mi = 0; mi < 4; mi++) {
        #pragma unroll
        for (int h = 0; h < 2; h++) {
            const int row = r0 + mi * 16 + h * 8;
            #pragma unroll
            for (int nj = 0; nj < 4; nj++) {
                const int col = c0 + nj * 8;
                float e = acc[mi][nj][h * 2]     + bias[col];
                float o = acc[mi][nj][h * 2 + 1] + bias[col + 1];
                if (EPI == 1) {
                    if (bn < 12) {   // q or k: RoPE
                        const int d = col & 63;
                        float sn = psin[(size_t)row * 64 + d];
                        float cs = pcos[(size_t)row * 64 + d];
                        float ne = e * cs - o * sn;
                        float no = o * cs + e * sn;
                        e = ne; o = no;
                        if (bn < 6) { e *= 0.125f; o *= 0.125f; }  // fold score scale into q (exact)
                    }
                    if (bn < 18) {   // q/k/v -> bf16 h/l qkv
                        __nv_bfloat16 h0, l0, h1, l1;
                        split_bf16(e, h0, l0);
                        split_bf16(o, h1, l1);
                        size_t qb = (size_t)row * QKVW + col;
                        *(uint32_t*)(qkvh + qb) = pack_b(h0, h1);
                        *(uint32_t*)(qkvl + qb) = pack_b(l0, l1);
                    } else {         // ff -> gelu -> bf16 h/l comb
                        float g0 = gelu_tanh(e), g1 = gelu_tanh(o);
                        __nv_bfloat16 h0, l0, h1, l1;
                        split_bf16(g0, h0, l0);
                        split_bf16(g1, h1, l1);
                        size_t cb = (size_t)row * COMBW + (col - 1536);
                        *(uint32_t*)(Ch + cb) = pack_b(h0, h1);
                        *(uint32_t*)(Cl + cb) = pack_b(l0, l1);
                    }
                } else {
                    const float* rp = resid + (size_t)row * HID + col;
                    *(float2*)(outp + (size_t)row * HID + col) =
                        make_float2(e + rp[0], o + rp[1]);
                }
            }
        }
    }
}

// ============================================================
// HMMA flash attention: block = (chunk of 256 q, head), 8 warps.
// Q staged in smem (64KB, bf16 h/l); 16 key tiles of 32, cp.async
// double-buffered. 3-term bf16 split for QK^T and PV.
// smem: [0,32K) Qh, [32K,64K) Ql, [64K, 64K+2*16K) KV stages
//       stage: Kh(4K) Kl(4K) Vh(4K) Vl(4K)
// ============================================================
#define ATTN_SMEM (65536 + 2 * 16384)

__global__ __launch_bounds__(256, 1) void attn_kernel(
    const int* __restrict__ lenp,
    const __nv_bfloat16* __restrict__ qvh, const __nv_bfloat16* __restrict__ qvl,
    __nv_bfloat16* __restrict__ Ch, __nv_bfloat16* __restrict__ Cl)
{
    extern __shared__ char smem[];
    const uint32_t sb = smem_to_u32(smem);
    const int c = blockIdx.x, head = blockIdx.y;
    const int tid = threadIdx.x, w = tid >> 5, lane = tid & 31;
    const int lm_mat = lane >> 3, lm_r = lane & 7;
    const unsigned lm = ~((unsigned)(*lenp) - 1u);
    const int base = c * 256 - 256;

    // ---- stage Q (h/l) ----
    {
        const int row = tid;
        const size_t qb = (size_t)(c * 256 + row) * QKVW + head * 64;
        #pragma unroll
        for (int i = 0; i < 8; i++) {
            uint32_t so = SMEM_SWIZZLE_128B((uint32_t)(row * 128 + i * 16));
            *(uint4*)(smem + so)         = *(const uint4*)(qvh + qb + i * 8);
            *(uint4*)(smem + 32768 + so) = *(const uint4*)(qvl + qb + i * 8);
        }
    }

    const int krow = tid >> 3, kch = tid & 7;
    const uint32_t kso = SMEM_SWIZZLE_128B((uint32_t)(krow * 128 + kch * 16));

    #define PREFETCH(kt) do {                                                       \
        int key = base + (kt) * 32 + krow;                                          \
        int sz = (key >= 0) ? 16 : 0;                                               \
        int cky = (key < 0) ? 0 : key;                                              \
        size_t kb_ = (size_t)cky * QKVW + HID + head * 64 + kch * 8;                \
        size_t vb_ = kb_ + HID;                                                     \
        uint32_t d = sb + 65536 + ((kt) & 1) * 16384 + kso;                         \
        cp_async16z(d,         qvh + kb_, sz);                                      \
        cp_async16z(d + 4096,  qvl + kb_, sz);                                      \
        cp_async16z(d + 8192,  qvh + vb_, sz);                                      \
        cp_async16z(d + 12288, qvl + vb_, sz);                                      \
        CP_COMMIT();                                                                \
    } while (0)

    float o[2][8][4];
    #pragma unroll
    for (int mi = 0; mi < 2; mi++)
        #pragma unroll
        for (int dj = 0; dj < 8; dj++)
            #pragma unroll
            for (int e = 0; e < 4; e++) o[mi][dj][e] = 0.f;
    float m[2][2] = {{-1e30f, -1e30f}, {-1e30f, -1e30f}};
    float lp[2][2] = {{0.f, 0.f}, {0.f, 0.f}};

    const int qrow0 = c * 256 + w * 32 + (lane >> 2);

    PREFETCH(0);

    for (int kt = 0; kt < 16; kt++) {
        if (kt + 1 < 16) {
            PREFETCH(kt + 1);
            asm volatile("cp.async.wait_group 1;" ::: "memory");
        } else {
            asm volatile("cp.async.wait_group 0;" ::: "memory");
        }
        __syncthreads();

        if (kt >= w && kt <= w + 8) {   // warp-level live window
            const uint32_t stg = sb + 65536 + (kt & 1) * 16384;

            // ---- S = Q @ K^T (3-term) ----
            float s[2][4][4];
            #pragma unroll
            for (int mi = 0; mi < 2; mi++)
                #pragma unroll
                for (int nj = 0; nj < 4; nj++)
                    #pragma unroll
                    for (int e = 0; e < 4; e++) s[mi][nj][e] = 0.f;

            #pragma unroll
            for (int ks = 0; ks < 4; ks++) {
                uint32_t qh[2][4], ql[2][4], kh[4][2], kl[4][2];
                #pragma unroll
                for (int mi = 0; mi < 2; mi++) {
                    int arow = w * 32 + mi * 16 + lm_r + (lm_mat & 1) * 8;
                    uint32_t so = SMEM_SWIZZLE_128B(
                        (uint32_t)(arow * 128 + (ks * 16 + (lm_mat >> 1) * 8) * 2));
                    ldsm4(qh[mi], sb + so);
                    ldsm4(ql[mi], sb + 32768 + so);
                }
                #pragma unroll
                for (int jp = 0; jp < 2; jp++) {
                    int krw = (jp * 2 + (lm_mat >> 1)) * 8 + lm_r;
                    uint32_t so = SMEM_SWIZZLE_128B(
                        (uint32_t)(krw * 128 + (ks * 16 + (lm_mat & 1) * 8) * 2));
                    uint32_t t[4];
                    ldsm4(t, stg + so);
                    kh[jp * 2][0] = t[0]; kh[jp * 2][1] = t[1];
                    kh[jp * 2 + 1][0] = t[2]; kh[jp * 2 + 1][1] = t[3];
                    ldsm4(t, stg + 4096 + so);
                    kl[jp * 2][0] = t[0]; kl[jp * 2][1] = t[1];
                    kl[jp * 2 + 1][0] = t[2]; kl[jp * 2 + 1][1] = t[3];
                }
                #pragma unroll
                for (int mi = 0; mi < 2; mi++)
                    #pragma unroll
                    for (int nj = 0; nj < 4; nj++) {
                        mma16816(s[mi][nj], qh[mi], kh[nj]);
                        mma16816(s[mi][nj], qh[mi], kl[nj]);
                        mma16816(s[mi][nj], ql[mi], kh[nj]);
                    }
            }

            // ---- mask + online softmax ----
            const int kB = base + kt * 32 + (lane & 3) * 2;
            float tm[2][2] = {{-1e30f, -1e30f}, {-1e30f, -1e30f}};
            #pragma unroll
            for (int mi = 0; mi < 2; mi++)
                #pragma unroll
                for (int nj = 0; nj < 4; nj++)
                    #pragma unroll
                    for (int e = 0; e < 4; e++) {
                        int hf = e >> 1;
                        int qi = qrow0 + mi * 16 + hf * 8;
                        int kabs = kB + nj * 8 + (e & 1);
                        int dd = qi - kabs;
                        bool ok = (kabs >= 0) && (dd >= 0) && (dd < 256) &&
                                  (((unsigned)qi & lm) == ((unsigned)kabs & lm));
                        float sv = ok ? s[mi][nj][e] : -1e30f;
                        s[mi][nj][e] = sv;
                        tm[mi][hf] = fmaxf(tm[mi][hf], sv);
                    }
            float corr[2][2];
            #pragma unroll
            for (int mi = 0; mi < 2; mi++)
                #pragma unroll
                for (int hf = 0; hf < 2; hf++) {
                    float t = tm[mi][hf];
                    t = fmaxf(t, __shfl_xor_sync(0xffffffffu, t, 1));
                    t = fmaxf(t, __shfl_xor_sync(0xffffffffu, t, 2));
                    float mn = fmaxf(fmaxf(m[mi][hf], t), -1e20f);
                    corr[mi][hf] = __expf(m[mi][hf] - mn);
                    m[mi][hf] = mn;
                    lp[mi][hf] *= corr[mi][hf];
                }
            #pragma unroll
            for (int mi = 0; mi < 2; mi++)
                #pragma unroll
                for (int dj = 0; dj < 8; dj++)
                    #pragma unroll
                    for (int e = 0; e < 4; e++) o[mi][dj][e] *= corr[mi][e >> 1];
            #pragma unroll
            for (int mi = 0; mi < 2; mi++)
                #pragma unroll
                for (int nj = 0; nj < 4; nj++)
                    #pragma unroll
                    for (int e = 0; e < 4; e++) {
                        float p = __expf(s[mi][nj][e] - m[mi][e >> 1]);
                        s[mi][nj][e] = p;
                        lp[mi][e >> 1] += p;
                    }

            // ---- O += P @ V (3-term, V via ldmatrix.trans) ----
            const uint32_t vB = stg + 8192;
            #pragma unroll
            for (int kv = 0; kv < 2; kv++) {
                uint32_t ah[2][4], al[2][4];
                #pragma unroll
                for (int mi = 0; mi < 2; mi++) {
                    const float* p0 = s[mi][2 * kv];
                    const float* p1 = s[mi][2 * kv + 1];
                    __nv_bfloat16 h[8], l[8];
                    #pragma unroll
                    for (int e = 0; e < 4; e++) {
                        split_bf16(p0[e], h[e], l[e]);
                        split_bf16(p1[e], h[4 + e], l[4 + e]);
                    }
                    ah[mi][0] = pack_b(h[0], h[1]); ah[mi][1] = pack_b(h[2], h[3]);
                    ah[mi][2] = pack_b(h[4], h[5]); ah[mi][3] = pack_b(h[6], h[7]);
                    al[mi][0] = pack_b(l[0], l[1]); al[mi][1] = pack_b(l[2], l[3]);
                    al[mi][2] = pack_b(l[4], l[5]); al[mi][3] = pack_b(l[6], l[7]);
                }
                #pragma unroll
                for (int djp = 0; djp < 4; djp++) {
                    int vrow = kv * 16 + (lm_mat & 1) * 8 + lm_r;
                    int vcb  = djp * 32 + (lm_mat >> 1) * 16;
                    uint32_t so = SMEM_SWIZZLE_128B((uint32_t)(vrow * 128 + vcb));
                    uint32_t th[4], tl[4];
                    ldsm4t(th, vB + so);
                    ldsm4t(tl, vB + 4096 + so);
                    #pragma unroll
                    for (int jj = 0; jj < 2; jj++) {
                        uint32_t bh[2] = { th[jj * 2], th[jj * 2 + 1] };
                        uint32_t bl[2] = { tl[jj * 2], tl[jj * 2 + 1] };
                        int dj = djp * 2 + jj;
                        #pragma unroll
                        for (int mi = 0; mi < 2; mi++) {
                            mma16816(o[mi][dj], ah[mi], bh);
                            mma16816(o[mi][dj], ah[mi], bl);
                            mma16816(o[mi][dj], al[mi], bh);
                        }
                    }
                }
            }
        }
        __syncthreads();
    }
    #undef PREFETCH

    // ---- normalize + write out ----
    float inv[2][2];
    #pragma unroll
    for (int mi = 0; mi < 2; mi++)
        #pragma unroll
        for (int hf = 0; hf < 2; hf++) {
            float l = lp[mi][hf];
            l += __shfl_xor_sync(0xffffffffu, l, 1);
            l += __shfl_xor_sync(0xffffffffu, l, 2);
            inv[mi][hf] = 1.f / l;
        }
    #pragma unroll
    for (int mi = 0; mi < 2; mi++)
        #pragma unroll
        for (int hf = 0; hf < 2; hf++) {
            const int qi = qrow0 + mi * 16 + hf * 8;
            const size_t ob = (size_t)qi * COMBW + head * 64 + (lane & 3) * 2;
            #pragma unroll
            for (int dj = 0; dj < 8; dj++) {
                float e0 = o[mi][dj][hf * 2]     * inv[mi][hf];
                float e1 = o[mi][dj][hf * 2 + 1] * inv[mi][hf];
                __nv_bfloat16 h0, l0, h1, l1;
                split_bf16(e0, h0, l0);
                split_bf16(e1, h1, l1);
                *(uint32_t*)(Ch + ob + dj * 8) = pack_b(h0, h1);
                *(uint32_t*)(Cl + ob + dj * 8) = pack_b(l0, l1);
            }
        }
}

// ============================================================
extern "C" void kernel_launch(void* const* d_in, const int* in_sizes, int n_in,
                              void* d_out, int out_size)
{
    const float* x     = (const float*)d_in[0];
    const float* psin  = (const float*)d_in[2];
    const float* pcos  = (const float*)d_in[3];
    const float* gamma = (const float*)d_in[4];
    const float* beta  = (const float*)d_in[5];
    const float* w_in  = (const float*)d_in[6];
    const float* b_in  = (const float*)d_in[7];
    const float* w_out = (const float*)d_in[8];
    const float* b_out = (const float*)d_in[9];
    const int*   lenp  = (const int*)d_in[10];
    float* out = (float*)d_out;

    float *xn;
    __nv_bfloat16 *xh, *xl, *qh, *ql, *ch, *cl, *wih, *wil, *woh, *wol;
    cudaGetSymbolAddress((void**)&xn,  g_xn);
    cudaGetSymbolAddress((void**)&xh,  g_xn_h);
    cudaGetSymbolAddress((void**)&xl,  g_xn_l);
    cudaGetSymbolAddress((void**)&qh,  g_qkv_h);
    cudaGetSymbolAddress((void**)&ql,  g_qkv_l);
    cudaGetSymbolAddress((void**)&ch,  g_cmb_h);
    cudaGetSymbolAddress((void**)&cl,  g_cmb_l);
    cudaGetSymbolAddress((void**)&wih, g_winT_h);
    cudaGetSymbolAddress((void**)&wil, g_winT_l);
    cudaGetSymbolAddress((void**)&woh, g_woutT_h);
    cudaGetSymbolAddress((void**)&wol, g_woutT_l);

    cudaFuncSetAttribute(gemm_kernel<1>, cudaFuncAttributeMaxDynamicSharedMemorySize, GEMM_SMEM);
    cudaFuncSetAttribute(gemm_kernel<0>, cudaFuncAttributeMaxDynamicSharedMemorySize, GEMM_SMEM);
    cudaFuncSetAttribute(attn_kernel,    cudaFuncAttributeMaxDynamicSharedMemorySize, ATTN_SMEM);

    ln_kernel<<<N_TOK, 256>>>(x, gamma, beta, xn, xh, xl);
    wtr_kernel<<<dim3(MIDW / 32, HID / 32), 256>>>(w_in, wih, wil, HID, MIDW);
    wtr_kernel<<<dim3(HID / 32, COMBW / 32), 256>>>(w_out, woh, wol, COMBW, HID);

    gemm_kernel<1><<<dim3(MIDW / 128, N_TOK / 128), 256, GEMM_SMEM>>>(
        xh, xl, wih, wil, HID, b_in, psin, pcos, qh, ql, ch, cl, nullptr, nullptr);

    attn_kernel<<<dim3(N_TOK / 256, NH), 256, ATTN_SMEM>>>(lenp, qh, ql, ch, cl);

    gemm_kernel<0><<<dim3(HID / 128, N_TOK / 128), 256, GEMM_SMEM>>>(
        ch, cl, woh, wol, COMBW, b_out, nullptr, nullptr, nullptr, nullptr, nullptr, nullptr, xn, out);
}